// round 9
// baseline (speedup 1.0000x reference)
#include <cuda_runtime.h>

// Fixed shapes
#define N_TOK 4096          // B*S
#define DIM   1024
#define NE    8
#define CAP   1280
#define NEC   ((size_t)N_TOK * NE * CAP)   // 41,943,040 floats
#define ECD   ((size_t)NE * CAP * DIM)     // 10,485,760 floats

#define ZB      4096                       // zero blocks
#define ZITER   20                         // float4 stores per zero thread (w+m = 2*NEC/4)

#define NSLOT   (NE * CAP)                 // 10240
#define SPB     8                          // slots per batch block (MLP=8)
#define BB      (NSLOT / SPB)              // 1280 batch blocks

// Scratch (device globals; fully rewritten every replay -> graph-deterministic)
__device__ int      g_top[2][N_TOK];
__device__ float    g_prob[2][N_TOK];
__device__ int      g_slot_token[NSLOT];
__device__ unsigned g_tok_off[2][N_TOK];   // slot e*CAP+r; 0xFFFFFFFF = dropped
__device__ float    g_tok_val[2][N_TOK];

// ---------------------------------------------------------------------------
// Zero-fill weights+mask (335 MB). Pure streaming stores, branch A.
// ---------------------------------------------------------------------------
__global__ void __launch_bounds__(256) k_zero(float* __restrict__ out) {
    float4* dst = (float4*)out;
    unsigned t0 = blockIdx.x * 256 + threadIdx.x;
    const unsigned stride = ZB * 256;
    const float4 z = make_float4(0.f, 0.f, 0.f, 0.f);
#pragma unroll
    for (int k = 0; k < ZITER; k++)
        __stcs(&dst[t0 + (size_t)k * stride], z);
}

// ---------------------------------------------------------------------------
// Router logits + top-2 + softmax. Warp per token, w staged in smem. Branch B.
// ---------------------------------------------------------------------------
__global__ void __launch_bounds__(256) k_logits(const float* __restrict__ x,
                                                const float* __restrict__ w,
                                                float* __restrict__ logits_out) {
    __shared__ float4 ws4[NE * (DIM / 4)];   // 32 KB
    const int tid = threadIdx.x;
    const float4* w4 = (const float4*)w;
    for (int i = tid; i < NE * (DIM / 4); i += 256) ws4[i] = w4[i];
    __syncthreads();

    const int warp = tid >> 5, lane = tid & 31;
    const int n = blockIdx.x * 8 + warp;

    const float4* xr = (const float4*)(x + (size_t)n * DIM);
    float acc[NE];
#pragma unroll
    for (int e = 0; e < NE; e++) acc[e] = 0.f;

#pragma unroll
    for (int ii = 0; ii < (DIM / 4) / 32; ii++) {
        int i = lane + ii * 32;
        float4 xv = xr[i];
#pragma unroll
        for (int e = 0; e < NE; e++) {
            float4 wv = ws4[e * (DIM / 4) + i];
            acc[e] = fmaf(xv.x, wv.x, acc[e]);
            acc[e] = fmaf(xv.y, wv.y, acc[e]);
            acc[e] = fmaf(xv.z, wv.z, acc[e]);
            acc[e] = fmaf(xv.w, wv.w, acc[e]);
        }
    }
#pragma unroll
    for (int e = 0; e < NE; e++) {
#pragma unroll
        for (int o = 16; o > 0; o >>= 1)
            acc[e] += __shfl_down_sync(0xffffffffu, acc[e], o);
    }

    if (lane == 0) {
        int i0 = 0; float v0 = acc[0];
#pragma unroll
        for (int e = 1; e < NE; e++) if (acc[e] > v0) { v0 = acc[e]; i0 = e; }
        int i1 = -1; float v1 = -INFINITY;
#pragma unroll
        for (int e = 0; e < NE; e++)
            if (e != i0 && acc[e] > v1) { v1 = acc[e]; i1 = e; }
        float t   = expf(v1 - v0);
        float den = 1.f + t;
        g_top[0][n]  = i0;
        g_top[1][n]  = i1;
        g_prob[0][n] = 1.f / den;
        g_prob[1][n] = t / den;
#pragma unroll
        for (int e = 0; e < NE; e++) logits_out[(size_t)n * NE + e] = acc[e];
    }
}

// ---------------------------------------------------------------------------
// Ordered per-expert rank scan (k-major). 1 block, 1024 thr x 8. Scratch only:
// per-token offsets/values + slot->token map. No output writes (branch B).
// ---------------------------------------------------------------------------
__global__ void __launch_bounds__(1024) k_scan() {
    const int IPT = (2 * N_TOK) / 1024;   // 8
    const int tid  = threadIdx.x;
    const int lane = tid & 31, warp = tid >> 5;

    for (int i = tid; i < NSLOT; i += 1024) g_slot_token[i] = -1;
    __syncthreads();

    int cnt[NE];
#pragma unroll
    for (int e = 0; e < NE; e++) cnt[e] = 0;
    int ex[IPT];
    const int j0 = tid * IPT;
#pragma unroll
    for (int i = 0; i < IPT; i++) {
        int j = j0 + i;
        int k = (j >= N_TOK) ? 1 : 0;
        int n = j - k * N_TOK;
        int e = g_top[k][n];
        ex[i] = e;
        cnt[e]++;
    }

    int incl[NE];
#pragma unroll
    for (int e = 0; e < NE; e++) {
        int v = cnt[e];
#pragma unroll
        for (int o = 1; o < 32; o <<= 1) {
            int u = __shfl_up_sync(0xffffffffu, v, o);
            if (lane >= o) v += u;
        }
        incl[e] = v;
    }

    __shared__ int wtot[32][NE];
    __shared__ int wbase[32][NE];
    if (lane == 31) {
#pragma unroll
        for (int e = 0; e < NE; e++) wtot[warp][e] = incl[e];
    }
    __syncthreads();
    if (warp == 0) {
#pragma unroll
        for (int e = 0; e < NE; e++) {
            int v = wtot[lane][e];
            int iv = v;
#pragma unroll
            for (int o = 1; o < 32; o <<= 1) {
                int u = __shfl_up_sync(0xffffffffu, iv, o);
                if (lane >= o) iv += u;
            }
            wbase[lane][e] = iv - v;
        }
    }
    __syncthreads();

    int base[NE];
#pragma unroll
    for (int e = 0; e < NE; e++) base[e] = wbase[warp][e] + incl[e] - cnt[e];

#pragma unroll
    for (int i = 0; i < IPT; i++) {
        int j = j0 + i;
        int k = (j >= N_TOK) ? 1 : 0;
        int n = j - k * N_TOK;
        int e = ex[i];
        int r = base[e]++;
        float p = g_prob[k][n];
        unsigned off = 0xFFFFFFFFu;
        if (r < CAP && p > 0.f) {
            off = (unsigned)(e * CAP + r);
            g_slot_token[off] = n;
        }
        g_tok_off[k][n] = off;
        g_tok_val[k][n] = p;
    }
}

// ---------------------------------------------------------------------------
// Tail (after join): expert batches (MLP=8 pull) + nonzero w/m patch.
// blocks [0, BB): 8 slots each. block BB: patch the 16K nonzero w/m entries.
// ---------------------------------------------------------------------------
__global__ void __launch_bounds__(256) k_tail(const float* __restrict__ x,
                                              float* __restrict__ out_w,
                                              float* __restrict__ out_m,
                                              float* __restrict__ out_b) {
    const int t = threadIdx.x;

    if (blockIdx.x == BB) {
        // patch: 2*N_TOK entries, coalesced-ish scattered scalar stores
        for (int j = t; j < 2 * N_TOK; j += 256) {
            int k = (j >= N_TOK) ? 1 : 0;
            int n = j - k * N_TOK;
            unsigned off = g_tok_off[k][n];
            if (off != 0xFFFFFFFFu) {
                size_t idx = (size_t)n * (NE * CAP) + off;
                out_w[idx] = g_tok_val[k][n];
                out_m[idx] = 1.0f;
            }
        }
        return;
    }

    const int s0 = blockIdx.x * SPB;
    const float4* xp = (const float4*)x;
    const float4 z = make_float4(0.f, 0.f, 0.f, 0.f);

    int nn[SPB];
#pragma unroll
    for (int j = 0; j < SPB; j++) nn[j] = g_slot_token[s0 + j];

    float4 v[SPB];
#pragma unroll
    for (int j = 0; j < SPB; j++)
        v[j] = (nn[j] >= 0) ? __ldg(&xp[(size_t)nn[j] * (DIM / 4) + t]) : z;

    float4* ob = (float4*)out_b;
#pragma unroll
    for (int j = 0; j < SPB; j++)
        __stcs(&ob[(size_t)(s0 + j) * (DIM / 4) + t], v[j]);
}

// ---------------------------------------------------------------------------
extern "C" void kernel_launch(void* const* d_in, const int* in_sizes, int n_in,
                              void* d_out, int out_size) {
    const float* x = (const float*)d_in[0];
    const float* w = (const float*)d_in[1];
    if (in_sizes[0] == NE * DIM && in_sizes[1] == N_TOK * DIM) {
        const float* tmp = x; x = w; w = tmp;
    }

    float* out   = (float*)d_out;          // [N,E,cap] w | [N,E,cap] m | [E,cap,D] b | [B,S,E] l
    float* out_w = out;
    float* out_m = out + NEC;
    float* out_b = out + 2 * NEC;
    float* out_l = out + 2 * NEC + ECD;

    // lazy one-time stream/event setup (first call is the non-captured
    // correctness run; replays use the captured branched graph)
    static cudaStream_t s2 = nullptr;
    static cudaEvent_t evFork = nullptr, evJoin = nullptr;
    if (s2 == nullptr) {
        cudaStreamCreateWithFlags(&s2, cudaStreamNonBlocking);
        cudaEventCreateWithFlags(&evFork, cudaEventDisableTiming);
        cudaEventCreateWithFlags(&evJoin, cudaEventDisableTiming);
    }

    // fork: branch B (logits -> scan) runs concurrently with branch A (zero)
    cudaEventRecord(evFork, 0);
    cudaStreamWaitEvent(s2, evFork, 0);

    k_logits<<<N_TOK / 8, 256, 0, s2>>>(x, w, out_l);
    k_scan<<<1, 1024, 0, s2>>>();
    cudaEventRecord(evJoin, s2);

    k_zero<<<ZB, 256>>>(out);              // branch A: 335 MB w+m zero

    // join: tail needs scan results AND the zeroed w/m region
    cudaStreamWaitEvent(0, evJoin, 0);
    k_tail<<<BB + 1, 256>>>(x, out_w, out_m, out_b);
}

// round 11
// speedup vs baseline: 1.2203x; 1.2203x over previous
#include <cuda_runtime.h>

// Fixed shapes
#define N_TOK 4096          // B*S
#define DIM   1024
#define NE    8
#define CAP   1280
#define NEC   ((size_t)N_TOK * NE * CAP)   // 41,943,040 floats
#define ECD   ((size_t)NE * CAP * DIM)     // 10,485,760 floats

#define ROW     (NE * CAP)                 // 10240 floats per token row
#define ROW_F4  (ROW / 4)                  // 2560

#define LB      512                        // logits blocks in K1
#define ZB1     2048                       // mask-zero blocks in K1
#define ZITER   20                         // f4 stores per zero thread: 2048*256*20 = NEC/4

#define NSLOT   (NE * CAP)                 // 10240
#define SPB     4
#define BB      (NSLOT / SPB)              // 2560 batch blocks in K3
#define K3GRID  (BB + N_TOK)               // + 4096 w-row blocks

// Scratch (device globals; fully rewritten every replay -> graph-deterministic)
__device__ int      g_top[2][N_TOK];
__device__ float    g_prob[2][N_TOK];
__device__ int      g_slot_token[NSLOT];
__device__ unsigned g_tok_off[2][N_TOK];   // within-row slot e*CAP+r; 0xFFFFFFFF = dropped
__device__ float    g_tok_val[2][N_TOK];

// ---------------------------------------------------------------------------
// K1: blocks [0,LB) = router logits (warp/token, w in smem);
//     blocks [LB,LB+ZB1) = zero the MASK region (167 MB streaming).
// ---------------------------------------------------------------------------
__global__ void __launch_bounds__(256) k_main(const float* __restrict__ x,
                                              const float* __restrict__ w,
                                              float* __restrict__ out_m,
                                              float* __restrict__ logits_out) {
    if (blockIdx.x >= LB) {
        float4* dst = (float4*)out_m;
        unsigned t0 = (blockIdx.x - LB) * 256 + threadIdx.x;
        const unsigned stride = ZB1 * 256;
        const float4 z = make_float4(0.f, 0.f, 0.f, 0.f);
#pragma unroll
        for (int k = 0; k < ZITER; k++)
            __stcs(&dst[t0 + (size_t)k * stride], z);
        return;
    }

    __shared__ float4 ws4[NE * (DIM / 4)];   // 32 KB
    const int tid = threadIdx.x;
    const float4* w4 = (const float4*)w;
    for (int i = tid; i < NE * (DIM / 4); i += 256) ws4[i] = w4[i];
    __syncthreads();

    const int warp = tid >> 5, lane = tid & 31;
    const int n = blockIdx.x * 8 + warp;

    const float4* xr = (const float4*)(x + (size_t)n * DIM);
    float acc[NE];
#pragma unroll
    for (int e = 0; e < NE; e++) acc[e] = 0.f;

#pragma unroll
    for (int ii = 0; ii < (DIM / 4) / 32; ii++) {
        int i = lane + ii * 32;
        float4 xv = xr[i];
#pragma unroll
        for (int e = 0; e < NE; e++) {
            float4 wv = ws4[e * (DIM / 4) + i];
            acc[e] = fmaf(xv.x, wv.x, acc[e]);
            acc[e] = fmaf(xv.y, wv.y, acc[e]);
            acc[e] = fmaf(xv.z, wv.z, acc[e]);
            acc[e] = fmaf(xv.w, wv.w, acc[e]);
        }
    }
#pragma unroll
    for (int e = 0; e < NE; e++) {
#pragma unroll
        for (int o = 16; o > 0; o >>= 1)
            acc[e] += __shfl_down_sync(0xffffffffu, acc[e], o);
    }

    if (lane == 0) {
        // top-2, jax.lax.top_k tie-break (lowest index wins)
        int i0 = 0; float v0 = acc[0];
#pragma unroll
        for (int e = 1; e < NE; e++) if (acc[e] > v0) { v0 = acc[e]; i0 = e; }
        int i1 = -1; float v1 = -INFINITY;
#pragma unroll
        for (int e = 0; e < NE; e++)
            if (e != i0 && acc[e] > v1) { v1 = acc[e]; i1 = e; }
        float t   = expf(v1 - v0);          // <= 1
        float den = 1.f + t;
        g_top[0][n]  = i0;
        g_top[1][n]  = i1;
        g_prob[0][n] = 1.f / den;
        g_prob[1][n] = t / den;
#pragma unroll
        for (int e = 0; e < NE; e++) logits_out[(size_t)n * NE + e] = acc[e];
    }
}

// ---------------------------------------------------------------------------
// K2: ordered per-expert rank scan (k-major). 1 block, 1024 thr x 8 items.
// Writes scratch only: per-token slot offsets/values + slot->token map.
// ---------------------------------------------------------------------------
__global__ void __launch_bounds__(1024) k_scan() {
    const int IPT = (2 * N_TOK) / 1024;   // 8
    const int tid  = threadIdx.x;
    const int lane = tid & 31, warp = tid >> 5;

    for (int i = tid; i < NSLOT; i += 1024) g_slot_token[i] = -1;
    __syncthreads();

    int cnt[NE];
#pragma unroll
    for (int e = 0; e < NE; e++) cnt[e] = 0;
    int ex[IPT];
    const int j0 = tid * IPT;
#pragma unroll
    for (int i = 0; i < IPT; i++) {
        int j = j0 + i;
        int k = (j >= N_TOK) ? 1 : 0;
        int n = j - k * N_TOK;
        int e = g_top[k][n];
        ex[i] = e;
        cnt[e]++;
    }

    int incl[NE];
#pragma unroll
    for (int e = 0; e < NE; e++) {
        int v = cnt[e];
#pragma unroll
        for (int o = 1; o < 32; o <<= 1) {
            int u = __shfl_up_sync(0xffffffffu, v, o);
            if (lane >= o) v += u;
        }
        incl[e] = v;
    }

    __shared__ int wtot[32][NE];
    __shared__ int wbase[32][NE];
    if (lane == 31) {
#pragma unroll
        for (int e = 0; e < NE; e++) wtot[warp][e] = incl[e];
    }
    __syncthreads();
    if (warp == 0) {
#pragma unroll
        for (int e = 0; e < NE; e++) {
            int v = wtot[lane][e];
            int iv = v;
#pragma unroll
            for (int o = 1; o < 32; o <<= 1) {
                int u = __shfl_up_sync(0xffffffffu, iv, o);
                if (lane >= o) iv += u;
            }
            wbase[lane][e] = iv - v;
        }
    }
    __syncthreads();

    int base[NE];
#pragma unroll
    for (int e = 0; e < NE; e++) base[e] = wbase[warp][e] + incl[e] - cnt[e];

#pragma unroll
    for (int i = 0; i < IPT; i++) {
        int j = j0 + i;
        int k = (j >= N_TOK) ? 1 : 0;
        int n = j - k * N_TOK;
        int e = ex[i];
        int r = base[e]++;
        float p = g_prob[k][n];
        unsigned off = 0xFFFFFFFFu;
        if (r < CAP && p > 0.f) {
            off = (unsigned)(e * CAP + r);
            g_slot_token[off] = n;
        }
        g_tok_off[k][n] = off;
        g_tok_val[k][n] = p;
    }
}

// ---------------------------------------------------------------------------
// K3: one grid, two roles, no sync:
//  blocks [0, BB):        batch gather: 4 slots/block (latency hidden under
//                         the w-zero stream below)
//  blocks [BB, BB+N_TOK): zero one token's WEIGHT row with inline w-patch,
//                         plus <=2 scalar m-patches (m zeroed in K1)
// ---------------------------------------------------------------------------
__global__ void __launch_bounds__(256) k_finish(const float* __restrict__ x,
                                                float* __restrict__ out_w,
                                                float* __restrict__ out_m,
                                                float* __restrict__ out_b) {
    const int t = threadIdx.x;

    if (blockIdx.x < BB) {
        const int s0 = blockIdx.x * SPB;
        const float4* xp = (const float4*)x;
        const float4 z = make_float4(0.f, 0.f, 0.f, 0.f);

        int n0 = g_slot_token[s0 + 0];
        int n1 = g_slot_token[s0 + 1];
        int n2 = g_slot_token[s0 + 2];
        int n3 = g_slot_token[s0 + 3];

        float4 v0 = (n0 >= 0) ? xp[(size_t)n0 * (DIM / 4) + t] : z;
        float4 v1 = (n1 >= 0) ? xp[(size_t)n1 * (DIM / 4) + t] : z;
        float4 v2 = (n2 >= 0) ? xp[(size_t)n2 * (DIM / 4) + t] : z;
        float4 v3 = (n3 >= 0) ? xp[(size_t)n3 * (DIM / 4) + t] : z;

        float4* ob = (float4*)out_b;
        __stcs(&ob[(size_t)(s0 + 0) * (DIM / 4) + t], v0);
        __stcs(&ob[(size_t)(s0 + 1) * (DIM / 4) + t], v1);
        __stcs(&ob[(size_t)(s0 + 2) * (DIM / 4) + t], v2);
        __stcs(&ob[(size_t)(s0 + 3) * (DIM / 4) + t], v3);
        return;
    }

    // ---- weight-row zero + inline patch ----
    const int n = blockIdx.x - BB;
    const unsigned off0 = g_tok_off[0][n], off1 = g_tok_off[1][n];
    const float    p0   = g_tok_val[0][n], p1   = g_tok_val[1][n];
    const unsigned f0 = off0 >> 2, c0 = off0 & 3;
    const unsigned f1 = off1 >> 2, c1 = off1 & 3;

    float4* dw = (float4*)out_w + (size_t)n * ROW_F4;

#pragma unroll
    for (int k = 0; k < ROW_F4 / 256; k++) {   // 10 iterations
        unsigned f = k * 256 + t;
        float4 zw = make_float4(0.f, 0.f, 0.f, 0.f);
        if (f == f0) {
            if (c0 == 0) zw.x = p0; else if (c0 == 1) zw.y = p0;
            else if (c0 == 2) zw.z = p0; else zw.w = p0;
        }
        if (f == f1) {
            if (c1 == 0) zw.x = p1; else if (c1 == 1) zw.y = p1;
            else if (c1 == 2) zw.z = p1; else zw.w = p1;
        }
        __stcs(&dw[f], zw);
    }

    // m-patches (region zeroed by K1; one store per kept assignment)
    if (t == 0 && off0 != 0xFFFFFFFFu) out_m[(size_t)n * ROW + off0] = 1.0f;
    if (t == 1 && off1 != 0xFFFFFFFFu) out_m[(size_t)n * ROW + off1] = 1.0f;
}

// ---------------------------------------------------------------------------
extern "C" void kernel_launch(void* const* d_in, const int* in_sizes, int n_in,
                              void* d_out, int out_size) {
    const float* x = (const float*)d_in[0];
    const float* w = (const float*)d_in[1];
    if (in_sizes[0] == NE * DIM && in_sizes[1] == N_TOK * DIM) {
        const float* tmp = x; x = w; w = tmp;
    }

    float* out   = (float*)d_out;          // [N,E,cap] w | [N,E,cap] m | [E,cap,D] b | [B,S,E] l
    float* out_w = out;
    float* out_m = out + NEC;
    float* out_b = out + 2 * NEC;
    float* out_l = out + 2 * NEC + ECD;

    k_main<<<LB + ZB1, 256>>>(x, w, out_m, out_l);   // logits + zero mask region
    k_scan<<<1, 1024>>>();
    k_finish<<<K3GRID, 256>>>(x, out_w, out_m, out_b);
}